// round 2
// baseline (speedup 1.0000x reference)
#include <cuda_runtime.h>
#include <math.h>

#define Bn 4
#define Mn 1024
#define Nn 70
#define Dn 256
#define Hn 8
#define Ln 4
#define DFFn 1024
#define DKn 32

// ---------------- scratch (no cudaMalloc allowed) ----------------
__device__ float g_x[Bn * Mn * Dn];
__device__ float g_xn[Bn * Mn * Dn];
__device__ float g_q[Bn * Mn * Dn];
__device__ float g_k[Bn * Mn * Dn];
__device__ float g_v[Bn * Mn * Dn];
__device__ float g_att[Bn * Mn * Dn];
__device__ float g_hid[Bn * Mn * DFFn];
__device__ float g_scores[(size_t)Bn * Hn * Mn * Mn];
__device__ float g_stmp[(size_t)Bn * Mn * Mn];

// ---------------- embedding: fourier PE + char projection ----------------
__global__ void embed_kernel(const float* __restrict__ X,
                             const float* __restrict__ fW,
                             const float* __restrict__ fb,
                             const float* __restrict__ cW,
                             const float* __restrict__ cb) {
    int row = blockIdx.x;          // b*M + m
    int d = threadIdx.x;           // 0..255
    __shared__ float xr[Nn];
    if (d < Nn) xr[d] = X[(size_t)row * Nn + d];
    __syncthreads();

    int j = d & 127;
    float p = xr[0] * fW[j * 3 + 0] + xr[1] * fW[j * 3 + 1] + xr[2] * fW[j * 3 + 2] + fb[j];
    float pe = (d < 128 ? cosf(p) : sinf(p)) * 0.17677669529663687f;  // sqrt(2/64)

    float acc = cb[d] + pe;
#pragma unroll
    for (int c = 0; c < 64; c++) acc += xr[6 + c] * cW[c * Dn + d];
    g_x[(size_t)row * Dn + d] = acc;
}

// ---------------- layernorm over D=256, one block per row ----------------
__global__ void ln_kernel(const float* __restrict__ x,
                          const float* __restrict__ w,
                          const float* __restrict__ b,
                          float* __restrict__ out) {
    int row = blockIdx.x;
    int t = threadIdx.x;
    float v = x[(size_t)row * Dn + t];
    __shared__ float red[256];
    red[t] = v;
    __syncthreads();
    for (int s = 128; s > 0; s >>= 1) {
        if (t < s) red[t] += red[t + s];
        __syncthreads();
    }
    float mu = red[0] * (1.0f / Dn);
    __syncthreads();
    float dv = v - mu;
    red[t] = dv * dv;
    __syncthreads();
    for (int s = 128; s > 0; s >>= 1) {
        if (t < s) red[t] += red[t + s];
        __syncthreads();
    }
    float var = red[0] * (1.0f / Dn);
    float r = rsqrtf(var + 1e-5f);
    out[(size_t)row * Dn + t] = dv * r * w[t] + b[t];
}

// ---------------- high-throughput tiled GEMM device body ----------------
// BM x 128 tile, BK=16, 256 threads, (BM/16)x8 per thread, float4 loads.
// Requires: N multiple of 128 from bn, K multiple of 16, M multiple of BM.
template <int BM, bool GELU, bool RES>
__device__ __forceinline__ void gemm_dev(const float* __restrict__ A,
                                         const float* __restrict__ B,
                                         const float* __restrict__ bias,
                                         const float* __restrict__ res,
                                         float* __restrict__ C,
                                         int N, int K, int bm, int bn) {
    const int BN = 128, BK = 16;
    const int RM = BM / 16;
    __shared__ float As[BK][BM + 4];
    __shared__ float Bs[BK][BN];
    int tid = threadIdx.x;
    int tx = tid % 16, ty = tid / 16;
    float acc[RM][8];
#pragma unroll
    for (int i = 0; i < RM; i++)
#pragma unroll
        for (int j = 0; j < 8; j++) acc[i][j] = 0.f;

    for (int k0 = 0; k0 < K; k0 += BK) {
#pragma unroll
        for (int i = 0; i < BM / 64; i++) {
            int idx = tid + i * 256;
            int r = idx >> 2, c4 = (idx & 3) * 4;
            float4 a = *(const float4*)&A[(size_t)(bm + r) * K + k0 + c4];
            As[c4 + 0][r] = a.x;
            As[c4 + 1][r] = a.y;
            As[c4 + 2][r] = a.z;
            As[c4 + 3][r] = a.w;
        }
#pragma unroll
        for (int i = 0; i < 2; i++) {
            int idx = tid + i * 256;
            int r = idx >> 5, c4 = (idx & 31) * 4;
            *(float4*)&Bs[r][c4] = *(const float4*)&B[(size_t)(k0 + r) * N + bn + c4];
        }
        __syncthreads();
#pragma unroll
        for (int kk = 0; kk < BK; kk++) {
            float ar[RM], br[8];
#pragma unroll
            for (int i = 0; i < RM; i++) ar[i] = As[kk][ty * RM + i];
#pragma unroll
            for (int j = 0; j < 8; j++) br[j] = Bs[kk][tx * 8 + j];
#pragma unroll
            for (int i = 0; i < RM; i++)
#pragma unroll
                for (int j = 0; j < 8; j++) acc[i][j] += ar[i] * br[j];
        }
        __syncthreads();
    }
#pragma unroll
    for (int i = 0; i < RM; i++) {
        int r = bm + ty * RM + i;
#pragma unroll
        for (int j = 0; j < 8; j++) {
            int cn = bn + tx * 8 + j;
            float v = acc[i][j] + bias[cn];
            if (GELU) v = 0.5f * v * (1.0f + erff(v * 0.70710678118654752f));
            if (RES) v += res[(size_t)r * N + cn];
            C[(size_t)r * N + cn] = v;
        }
    }
}

template <int BM, bool GELU, bool RES>
__global__ void gemm_kernel(const float* __restrict__ A, const float* __restrict__ B,
                            const float* __restrict__ bias, const float* __restrict__ res,
                            float* __restrict__ C, int N, int K) {
    gemm_dev<BM, GELU, RES>(A, B, bias, res, C, N, K, blockIdx.y * BM, blockIdx.x * 128);
}

// QKV fused: blockIdx.z selects which of the three projections.
__global__ void qkv_kernel(const float* __restrict__ A,
                           const float* __restrict__ Wq, const float* __restrict__ bq,
                           const float* __restrict__ Wk, const float* __restrict__ bk,
                           const float* __restrict__ Wv, const float* __restrict__ bv,
                           float* __restrict__ q, float* __restrict__ k, float* __restrict__ v) {
    const float* B;
    const float* bias;
    float* C;
    if (blockIdx.z == 0) { B = Wq; bias = bq; C = q; }
    else if (blockIdx.z == 1) { B = Wk; bias = bk; C = k; }
    else { B = Wv; bias = bv; C = v; }
    gemm_dev<128, false, false>(A, B, bias, nullptr, C, Dn, Dn, blockIdx.y * 128, blockIdx.x * 128);
}

// ---------------- small GEMM for final projection (N=64) ----------------
__global__ void gemm64n_kernel(const float* __restrict__ A, const float* __restrict__ B,
                               const float* __restrict__ bias, float* __restrict__ C,
                               int N, int K) {
    const int BM = 64, BN = 64, BK = 16;
    __shared__ float As[BM][BK + 1];
    __shared__ float Bs[BK][BN];
    int bm = blockIdx.y * BM, bn = blockIdx.x * BN;
    int tid = threadIdx.x;
    int ty = tid / 16, tx = tid % 16;
    float acc[4][4] = {};
    for (int k0 = 0; k0 < K; k0 += BK) {
#pragma unroll
        for (int i = 0; i < 4; i++) {
            int idx = tid + i * 256;
            int r = idx / BK, c = idx % BK;
            As[r][c] = A[(size_t)(bm + r) * K + k0 + c];
        }
#pragma unroll
        for (int i = 0; i < 4; i++) {
            int idx = tid + i * 256;
            int r = idx / BN, c = idx % BN;
            Bs[r][c] = B[(size_t)(k0 + r) * N + bn + c];
        }
        __syncthreads();
#pragma unroll
        for (int kk = 0; kk < BK; kk++) {
            float a[4], bb[4];
#pragma unroll
            for (int i = 0; i < 4; i++) a[i] = As[ty * 4 + i][kk];
#pragma unroll
            for (int j = 0; j < 4; j++) bb[j] = Bs[kk][tx * 4 + j];
#pragma unroll
            for (int i = 0; i < 4; i++)
#pragma unroll
                for (int j = 0; j < 4; j++) acc[i][j] += a[i] * bb[j];
        }
        __syncthreads();
    }
#pragma unroll
    for (int i = 0; i < 4; i++) {
        int r = bm + ty * 4 + i;
#pragma unroll
        for (int j = 0; j < 4; j++) {
            int cn = bn + tx * 4 + j;
            C[(size_t)r * N + cn] = acc[i][j] + bias[cn];
        }
    }
}

// ---------------- fused flash attention ----------------
// Block: (q-tile of 64 rows, b*H+h). 256 threads = 8 warps; warp owns 8 q rows,
// lane owns one of 32 head dims. Online softmax; SAVE writes raw scaled scores.
template <bool SAVE>
__global__ void flash_kernel(const float* __restrict__ q, const float* __restrict__ k,
                             const float* __restrict__ v, const int* __restrict__ mask,
                             float* __restrict__ att, float* __restrict__ scores) {
    int bh = blockIdx.y;
    int b = bh / Hn, h = bh % Hn;
    int q0 = blockIdx.x * 64;
    __shared__ float Qs[64][33], Ks[64][33], Vs[64][33];
    __shared__ float ws[8][64];
    int tid = threadIdx.x;
    int wid = tid / 32, lane = tid % 32;

#pragma unroll
    for (int i = 0; i < 8; i++) {
        int idx = tid + i * 256;
        int r = idx >> 5, c = idx & 31;
        Qs[r][c] = q[(size_t)(b * Mn + q0 + r) * Dn + h * DKn + c];
    }

    float m_r[8], l_r[8], acc[8];
#pragma unroll
    for (int r = 0; r < 8; r++) { m_r[r] = -1e30f; l_r[r] = 0.f; acc[r] = 0.f; }

    const float sc = 0.17677669529663687f;  // 1/sqrt(32)

    for (int kt = 0; kt < Mn; kt += 64) {
#pragma unroll
        for (int i = 0; i < 8; i++) {
            int idx = tid + i * 256;
            int r = idx >> 5, c = idx & 31;
            size_t src = (size_t)(b * Mn + kt + r) * Dn + h * DKn + c;
            Ks[r][c] = k[src];
            Vs[r][c] = v[src];
        }
        __syncthreads();

#pragma unroll
        for (int r = 0; r < 8; r++) {
            int qq = wid * 8 + r;
            float s0 = 0.f, s1 = 0.f;
#pragma unroll
            for (int d = 0; d < 32; d++) {
                float qd = Qs[qq][d];
                s0 += qd * Ks[lane][d];
                s1 += qd * Ks[lane + 32][d];
            }
            s0 *= sc;
            s1 *= sc;
            if (SAVE) {
                size_t base = ((size_t)(b * Hn + h) * Mn + q0 + qq) * Mn + kt;
                scores[base + lane] = s0;
                scores[base + lane + 32] = s1;
            }
            const int* mrow = mask + ((size_t)(b * Mn + q0 + qq)) * Mn + kt;
            if (mrow[lane] == 0) s0 = -1e30f;
            if (mrow[lane + 32] == 0) s1 = -1e30f;

            float mx = fmaxf(s0, s1);
#pragma unroll
            for (int off = 16; off > 0; off >>= 1)
                mx = fmaxf(mx, __shfl_xor_sync(0xFFFFFFFFu, mx, off));
            float newm = fmaxf(m_r[r], mx);
            float p0 = __expf(s0 - newm);
            float p1 = __expf(s1 - newm);
            float rscale = __expf(m_r[r] - newm);
            float psum = p0 + p1;
#pragma unroll
            for (int off = 16; off > 0; off >>= 1)
                psum += __shfl_xor_sync(0xFFFFFFFFu, psum, off);
            l_r[r] = l_r[r] * rscale + psum;
            m_r[r] = newm;
            acc[r] *= rscale;

            ws[wid][lane] = p0;
            ws[wid][lane + 32] = p1;
            __syncwarp();
            float a = acc[r];
#pragma unroll
            for (int kk = 0; kk < 64; kk++) a += ws[wid][kk] * Vs[kk][lane];
            acc[r] = a;
            __syncwarp();
        }
        __syncthreads();
    }

#pragma unroll
    for (int r = 0; r < 8; r++) {
        float inv = 1.0f / l_r[r];
        att[(size_t)(b * Mn + q0 + wid * 8 + r) * Dn + h * DKn + lane] = acc[r] * inv;
    }
}

// ---------------- s head part 1: per (b,q,k) LN over H + projection ----------------
__global__ void spool_kernel(const float* __restrict__ scores, const float* __restrict__ snw,
                             const float* __restrict__ snb, const float* __restrict__ sfpw,
                             const float* __restrict__ sfpb, float* __restrict__ tmp) {
    size_t idx = (size_t)blockIdx.x * blockDim.x + threadIdx.x;
    if (idx >= (size_t)Bn * Mn * Mn) return;
    int k = idx % Mn;
    size_t r = idx / Mn;
    int qq = (int)(r % Mn);
    int b = (int)(r / Mn);
    float vals[8];
    float mu = 0.f;
#pragma unroll
    for (int h = 0; h < 8; h++) {
        vals[h] = scores[((size_t)(b * Hn + h) * Mn + qq) * Mn + k];
        mu += vals[h];
    }
    mu *= 0.125f;
    float var = 0.f;
#pragma unroll
    for (int h = 0; h < 8; h++) {
        float dd = vals[h] - mu;
        var += dd * dd;
    }
    var *= 0.125f;
    float rs = rsqrtf(var + 1e-5f);
    float o = sfpb[0];
#pragma unroll
    for (int h = 0; h < 8; h++) o += ((vals[h] - mu) * rs * snw[h] + snb[h]) * sfpw[h];
    tmp[idx] = o;
}

// ---------------- s head part 2: symmetrize ----------------
__global__ void ssym_kernel(const float* __restrict__ tmp, float* __restrict__ out) {
    size_t idx = (size_t)blockIdx.x * blockDim.x + threadIdx.x;
    if (idx >= (size_t)Bn * Mn * Mn) return;
    int k = idx % Mn;
    size_t r = idx / Mn;
    int qq = (int)(r % Mn);
    int b = (int)(r / Mn);
    out[idx] = 0.5f * (tmp[idx] + tmp[((size_t)b * Mn + k) * Mn + qq]);
}

// =====================================================================
extern "C" void kernel_launch(void* const* d_in, const int* in_sizes, int n_in,
                              void* d_out, int out_size) {
    const float* X   = (const float*)d_in[0];
    const int*   mask= (const int*)d_in[1];
    const float* fW  = (const float*)d_in[2];
    const float* fb  = (const float*)d_in[3];
    const float* cW  = (const float*)d_in[4];
    const float* cb  = (const float*)d_in[5];
    const float* Wq  = (const float*)d_in[6];
    const float* bq  = (const float*)d_in[7];
    const float* Wk  = (const float*)d_in[8];
    const float* bk  = (const float*)d_in[9];
    const float* Wv  = (const float*)d_in[10];
    const float* bv  = (const float*)d_in[11];
    const float* Wo  = (const float*)d_in[12];
    const float* bo  = (const float*)d_in[13];
    const float* ln1w= (const float*)d_in[14];
    const float* ln1b= (const float*)d_in[15];
    const float* ln2w= (const float*)d_in[16];
    const float* ln2b= (const float*)d_in[17];
    const float* lnfw= (const float*)d_in[18];
    const float* lnfb= (const float*)d_in[19];
    const float* uw  = (const float*)d_in[20];
    const float* ub  = (const float*)d_in[21];
    const float* dw  = (const float*)d_in[22];
    const float* db  = (const float*)d_in[23];
    const float* finw= (const float*)d_in[24];
    const float* finb= (const float*)d_in[25];
    const float* snw = (const float*)d_in[26];
    const float* snb = (const float*)d_in[27];
    const float* sfpw= (const float*)d_in[28];
    const float* sfpb= (const float*)d_in[29];

    float *x, *xn, *q, *k, *v, *att, *hid, *scores, *stmp;
    cudaGetSymbolAddress((void**)&x, g_x);
    cudaGetSymbolAddress((void**)&xn, g_xn);
    cudaGetSymbolAddress((void**)&q, g_q);
    cudaGetSymbolAddress((void**)&k, g_k);
    cudaGetSymbolAddress((void**)&v, g_v);
    cudaGetSymbolAddress((void**)&att, g_att);
    cudaGetSymbolAddress((void**)&hid, g_hid);
    cudaGetSymbolAddress((void**)&scores, g_scores);
    cudaGetSymbolAddress((void**)&stmp, g_stmp);

    const int BM = Bn * Mn;  // 4096 rows

    embed_kernel<<<BM, 256>>>(X, fW, fb, cW, cb);

    for (int i = 0; i < Ln; i++) {
        const float* Woi = Wo + (size_t)i * Dn * Dn;
        const float* uwi = uw + (size_t)i * Dn * DFFn;
        const float* dwi = dw + (size_t)i * DFFn * Dn;

        ln_kernel<<<BM, 256>>>(x, ln1w + i * Dn, ln1b + i * Dn, xn);

        dim3 gqkv(Dn / 128, BM / 128, 3);
        qkv_kernel<<<gqkv, 256>>>(xn,
                                  Wq + (size_t)i * Dn * Dn, bq + i * Dn,
                                  Wk + (size_t)i * Dn * Dn, bk + i * Dn,
                                  Wv + (size_t)i * Dn * Dn, bv + i * Dn,
                                  q, k, v);

        dim3 gfl(Mn / 64, Bn * Hn);
        if (i == Ln - 1)
            flash_kernel<true><<<gfl, 256>>>(q, k, v, mask, att, scores);
        else
            flash_kernel<false><<<gfl, 256>>>(q, k, v, mask, att, scores);

        dim3 go(Dn / 128, BM / 64);
        gemm_kernel<64, false, true><<<go, 256>>>(att, Woi, bo + i * Dn, x, x, Dn, Dn);

        ln_kernel<<<BM, 256>>>(x, ln2w + i * Dn, ln2b + i * Dn, xn);

        dim3 gu(DFFn / 128, BM / 128);
        gemm_kernel<128, true, false><<<gu, 256>>>(xn, uwi, ub + i * DFFn, nullptr, hid, DFFn, Dn);

        dim3 gd(Dn / 128, BM / 64);
        gemm_kernel<64, false, true><<<gd, 256>>>(hid, dwi, db + i * Dn, x, x, Dn, DFFn);
    }

    float* out_x = (float*)d_out;                    // (B, M, 64)
    float* out_s = out_x + (size_t)BM * 64;          // (B, M, M)

    ln_kernel<<<BM, 256>>>(x, lnfw, lnfb, xn);
    dim3 gf(1, BM / 64);
    gemm64n_kernel<<<gf, 256>>>(xn, finw, finb, out_x, 64, Dn);

    size_t npair = (size_t)Bn * Mn * Mn;
    int nb = (int)((npair + 255) / 256);
    spool_kernel<<<nb, 256>>>(scores, snw, snb, sfpw, sfpb, stmp);
    ssym_kernel<<<nb, 256>>>(stmp, out_s);
}

// round 3
// speedup vs baseline: 1.5307x; 1.5307x over previous
#include <cuda_runtime.h>
#include <math.h>

#define Bn 4
#define Mn 1024
#define Nn 70
#define Dn 256
#define Hn 8
#define Ln 4
#define DFFn 1024
#define DKn 32

// ---------------- scratch (no cudaMalloc allowed) ----------------
__device__ float g_x[Bn * Mn * Dn];
__device__ float g_xn[Bn * Mn * Dn];
__device__ float g_q[Bn * Mn * Dn];
__device__ float g_k[Bn * Mn * Dn];
__device__ float g_v[Bn * Mn * Dn];
__device__ float g_att[Bn * Mn * Dn];
__device__ float g_hid[Bn * Mn * DFFn];
__device__ float g_scores[(size_t)Bn * Hn * Mn * Mn];
__device__ float g_stmp[(size_t)Bn * Mn * Mn];

// ---------------- embedding: fourier PE + char projection ----------------
__global__ void embed_kernel(const float* __restrict__ X,
                             const float* __restrict__ fW,
                             const float* __restrict__ fb,
                             const float* __restrict__ cW,
                             const float* __restrict__ cb) {
    int row = blockIdx.x;          // b*M + m
    int d = threadIdx.x;           // 0..255
    __shared__ float xr[Nn];
    if (d < Nn) xr[d] = X[(size_t)row * Nn + d];
    __syncthreads();

    int j = d & 127;
    float p = xr[0] * fW[j * 3 + 0] + xr[1] * fW[j * 3 + 1] + xr[2] * fW[j * 3 + 2] + fb[j];
    float pe = (d < 128 ? cosf(p) : sinf(p)) * 0.17677669529663687f;  // sqrt(2/64)

    float acc = cb[d] + pe;
#pragma unroll
    for (int c = 0; c < 64; c++) acc += xr[6 + c] * cW[c * Dn + d];
    g_x[(size_t)row * Dn + d] = acc;
}

// ---------------- layernorm over D=256, one block per row ----------------
__global__ void ln_kernel(const float* __restrict__ x,
                          const float* __restrict__ w,
                          const float* __restrict__ b,
                          float* __restrict__ out) {
    int row = blockIdx.x;
    int t = threadIdx.x;
    float v = x[(size_t)row * Dn + t];
    __shared__ float red[256];
    red[t] = v;
    __syncthreads();
    for (int s = 128; s > 0; s >>= 1) {
        if (t < s) red[t] += red[t + s];
        __syncthreads();
    }
    float mu = red[0] * (1.0f / Dn);
    __syncthreads();
    float dv = v - mu;
    red[t] = dv * dv;
    __syncthreads();
    for (int s = 128; s > 0; s >>= 1) {
        if (t < s) red[t] += red[t + s];
        __syncthreads();
    }
    float var = red[0] * (1.0f / Dn);
    float r = rsqrtf(var + 1e-5f);
    out[(size_t)row * Dn + t] = dv * r * w[t] + b[t];
}

// ---------------- high-throughput tiled GEMM device body ----------------
template <int BM, bool GELU, bool RES>
__device__ __forceinline__ void gemm_dev(const float* __restrict__ A,
                                         const float* __restrict__ B,
                                         const float* __restrict__ bias,
                                         const float* __restrict__ res,
                                         float* __restrict__ C,
                                         int N, int K, int bm, int bn) {
    const int BN = 128, BK = 16;
    const int RM = BM / 16;
    __shared__ float As[BK][BM + 4];
    __shared__ float Bs[BK][BN];
    int tid = threadIdx.x;
    int tx = tid % 16, ty = tid / 16;
    float acc[RM][8];
#pragma unroll
    for (int i = 0; i < RM; i++)
#pragma unroll
        for (int j = 0; j < 8; j++) acc[i][j] = 0.f;

    for (int k0 = 0; k0 < K; k0 += BK) {
#pragma unroll
        for (int i = 0; i < BM / 64; i++) {
            int idx = tid + i * 256;
            int r = idx >> 2, c4 = (idx & 3) * 4;
            float4 a = *(const float4*)&A[(size_t)(bm + r) * K + k0 + c4];
            As[c4 + 0][r] = a.x;
            As[c4 + 1][r] = a.y;
            As[c4 + 2][r] = a.z;
            As[c4 + 3][r] = a.w;
        }
#pragma unroll
        for (int i = 0; i < 2; i++) {
            int idx = tid + i * 256;
            int r = idx >> 5, c4 = (idx & 31) * 4;
            *(float4*)&Bs[r][c4] = *(const float4*)&B[(size_t)(k0 + r) * N + bn + c4];
        }
        __syncthreads();
#pragma unroll
        for (int kk = 0; kk < BK; kk++) {
            float ar[RM], br[8];
#pragma unroll
            for (int i = 0; i < RM; i++) ar[i] = As[kk][ty * RM + i];
#pragma unroll
            for (int j = 0; j < 8; j++) br[j] = Bs[kk][tx * 8 + j];
#pragma unroll
            for (int i = 0; i < RM; i++)
#pragma unroll
                for (int j = 0; j < 8; j++) acc[i][j] += ar[i] * br[j];
        }
        __syncthreads();
    }
#pragma unroll
    for (int i = 0; i < RM; i++) {
        int r = bm + ty * RM + i;
#pragma unroll
        for (int j = 0; j < 8; j++) {
            int cn = bn + tx * 8 + j;
            float v = acc[i][j] + bias[cn];
            if (GELU) v = 0.5f * v * (1.0f + erff(v * 0.70710678118654752f));
            if (RES) v += res[(size_t)r * N + cn];
            C[(size_t)r * N + cn] = v;
        }
    }
}

template <int BM, bool GELU, bool RES>
__global__ void gemm_kernel(const float* __restrict__ A, const float* __restrict__ B,
                            const float* __restrict__ bias, const float* __restrict__ res,
                            float* __restrict__ C, int N, int K) {
    gemm_dev<BM, GELU, RES>(A, B, bias, res, C, N, K, blockIdx.y * BM, blockIdx.x * 128);
}

// QKV fused: blockIdx.z selects which of the three projections.
__global__ void qkv_kernel(const float* __restrict__ A,
                           const float* __restrict__ Wq, const float* __restrict__ bq,
                           const float* __restrict__ Wk, const float* __restrict__ bk,
                           const float* __restrict__ Wv, const float* __restrict__ bv,
                           float* __restrict__ q, float* __restrict__ k, float* __restrict__ v) {
    const float* B;
    const float* bias;
    float* C;
    if (blockIdx.z == 0) { B = Wq; bias = bq; C = q; }
    else if (blockIdx.z == 1) { B = Wk; bias = bk; C = k; }
    else { B = Wv; bias = bv; C = v; }
    gemm_dev<128, false, false>(A, B, bias, nullptr, C, Dn, Dn, blockIdx.y * 128, blockIdx.x * 128);
}

// ---------------- small GEMM for final projection (N=64) ----------------
__global__ void gemm64n_kernel(const float* __restrict__ A, const float* __restrict__ B,
                               const float* __restrict__ bias, float* __restrict__ C,
                               int N, int K) {
    const int BM = 64, BN = 64, BK = 16;
    __shared__ float As[BM][BK + 1];
    __shared__ float Bs[BK][BN];
    int bm = blockIdx.y * BM, bn = blockIdx.x * BN;
    int tid = threadIdx.x;
    int ty = tid / 16, tx = tid % 16;
    float acc[4][4] = {};
    for (int k0 = 0; k0 < K; k0 += BK) {
#pragma unroll
        for (int i = 0; i < 4; i++) {
            int idx = tid + i * 256;
            int r = idx / BK, c = idx % BK;
            As[r][c] = A[(size_t)(bm + r) * K + k0 + c];
        }
#pragma unroll
        for (int i = 0; i < 4; i++) {
            int idx = tid + i * 256;
            int r = idx / BN, c = idx % BN;
            Bs[r][c] = B[(size_t)(k0 + r) * N + bn + c];
        }
        __syncthreads();
#pragma unroll
        for (int kk = 0; kk < BK; kk++) {
            float a[4], bb[4];
#pragma unroll
            for (int i = 0; i < 4; i++) a[i] = As[ty * 4 + i][kk];
#pragma unroll
            for (int j = 0; j < 4; j++) bb[j] = Bs[kk][tx * 4 + j];
#pragma unroll
            for (int i = 0; i < 4; i++)
#pragma unroll
                for (int j = 0; j < 4; j++) acc[i][j] += a[i] * bb[j];
        }
        __syncthreads();
    }
#pragma unroll
    for (int i = 0; i < 4; i++) {
        int r = bm + ty * 4 + i;
#pragma unroll
        for (int j = 0; j < 4; j++) {
            int cn = bn + tx * 4 + j;
            C[(size_t)r * N + cn] = acc[i][j] + bias[cn];
        }
    }
}

// ---------------- fused flash attention v2 (register-tiled) ----------------
// Block = (64 q rows, one b*H+h). 256 threads as 16x16: ty owns 4 q rows,
// tx owns 4 k cols (score GEMM) / 2 d cols (PV GEMM). Online softmax with
// per-thread m/l for 4 q rows; half-warp shuffle reductions over tx.
template <bool SAVE>
__global__ void flash_kernel(const float* __restrict__ q, const float* __restrict__ k,
                             const float* __restrict__ v, const int* __restrict__ mask,
                             float* __restrict__ att, float* __restrict__ scores) {
    int bh = blockIdx.y;
    int b = bh / Hn, h = bh % Hn;
    int q0 = blockIdx.x * 64;
    __shared__ float Qs[64][33];
    __shared__ float Ks[64][33];
    __shared__ float Vs[64][34];   // even stride -> aligned float2 reads
    __shared__ float Ps[64][68];   // stride 68 floats = 272B (16B mult) -> aligned float4
    int tid = threadIdx.x;
    int tx = tid & 15, ty = tid >> 4;

    // load Q tile
#pragma unroll
    for (int i = 0; i < 8; i++) {
        int idx = tid + i * 256;
        int r = idx >> 5, c = idx & 31;
        Qs[r][c] = q[(size_t)(b * Mn + q0 + r) * Dn + h * DKn + c];
    }

    float m_r[4], l_r[4];
    float O[4][2];
#pragma unroll
    for (int i = 0; i < 4; i++) {
        m_r[i] = -1e30f;
        l_r[i] = 0.f;
        O[i][0] = 0.f;
        O[i][1] = 0.f;
    }

    const float sc = 0.17677669529663687f;  // 1/sqrt(32)

    for (int kt = 0; kt < Mn; kt += 64) {
        __syncthreads();  // protect Ks/Vs from previous iteration's readers
#pragma unroll
        for (int i = 0; i < 8; i++) {
            int idx = tid + i * 256;
            int r = idx >> 5, c = idx & 31;
            size_t src = (size_t)(b * Mn + kt + r) * Dn + h * DKn + c;
            Ks[r][c] = k[src];
            Vs[r][c] = v[src];
        }
        __syncthreads();

        // ---- score tile: S[4][4] ----
        float S[4][4];
#pragma unroll
        for (int i = 0; i < 4; i++)
#pragma unroll
            for (int j = 0; j < 4; j++) S[i][j] = 0.f;
#pragma unroll
        for (int c = 0; c < 32; c++) {
            float a[4], bb[4];
#pragma unroll
            for (int i = 0; i < 4; i++) a[i] = Qs[ty * 4 + i][c];
#pragma unroll
            for (int j = 0; j < 4; j++) bb[j] = Ks[tx * 4 + j][c];
#pragma unroll
            for (int i = 0; i < 4; i++)
#pragma unroll
                for (int j = 0; j < 4; j++) S[i][j] += a[i] * bb[j];
        }
#pragma unroll
        for (int i = 0; i < 4; i++)
#pragma unroll
            for (int j = 0; j < 4; j++) S[i][j] *= sc;

        if (SAVE) {
#pragma unroll
            for (int i = 0; i < 4; i++) {
                size_t base = ((size_t)bh * Mn + q0 + ty * 4 + i) * Mn + kt + tx * 4;
                *(float4*)&scores[base] = make_float4(S[i][0], S[i][1], S[i][2], S[i][3]);
            }
        }

        // ---- mask ----
#pragma unroll
        for (int i = 0; i < 4; i++) {
            const int4 mr = *(const int4*)&mask[((size_t)(b * Mn + q0 + ty * 4 + i)) * Mn + kt + tx * 4];
            if (mr.x == 0) S[i][0] = -1e30f;
            if (mr.y == 0) S[i][1] = -1e30f;
            if (mr.z == 0) S[i][2] = -1e30f;
            if (mr.w == 0) S[i][3] = -1e30f;
        }

        // ---- online softmax update ----
        float rs[4];
#pragma unroll
        for (int i = 0; i < 4; i++) {
            float mx = fmaxf(fmaxf(S[i][0], S[i][1]), fmaxf(S[i][2], S[i][3]));
#pragma unroll
            for (int off = 8; off > 0; off >>= 1)
                mx = fmaxf(mx, __shfl_xor_sync(0xFFFFFFFFu, mx, off));
            float newm = fmaxf(m_r[i], mx);
            float psum = 0.f;
#pragma unroll
            for (int j = 0; j < 4; j++) {
                S[i][j] = __expf(S[i][j] - newm);
                psum += S[i][j];
            }
#pragma unroll
            for (int off = 8; off > 0; off >>= 1)
                psum += __shfl_xor_sync(0xFFFFFFFFu, psum, off);
            rs[i] = __expf(m_r[i] - newm);
            l_r[i] = l_r[i] * rs[i] + psum;
            m_r[i] = newm;
            O[i][0] *= rs[i];
            O[i][1] *= rs[i];
        }

        // ---- write P, sync half-warp producers/consumers ----
#pragma unroll
        for (int i = 0; i < 4; i++) {
            Ps[ty * 4 + i][tx * 4 + 0] = S[i][0];
            Ps[ty * 4 + i][tx * 4 + 1] = S[i][1];
            Ps[ty * 4 + i][tx * 4 + 2] = S[i][2];
            Ps[ty * 4 + i][tx * 4 + 3] = S[i][3];
        }
        __syncwarp();

        // ---- PV: O[4][2] += P[64] x V[64][2] ----
#pragma unroll 4
        for (int kk = 0; kk < 64; kk += 4) {
            float4 p0 = *(const float4*)&Ps[ty * 4 + 0][kk];
            float4 p1 = *(const float4*)&Ps[ty * 4 + 1][kk];
            float4 p2 = *(const float4*)&Ps[ty * 4 + 2][kk];
            float4 p3 = *(const float4*)&Ps[ty * 4 + 3][kk];
            float2 v0 = *(const float2*)&Vs[kk + 0][tx * 2];
            float2 v1 = *(const float2*)&Vs[kk + 1][tx * 2];
            float2 v2 = *(const float2*)&Vs[kk + 2][tx * 2];
            float2 v3 = *(const float2*)&Vs[kk + 3][tx * 2];
            O[0][0] += p0.x * v0.x + p0.y * v1.x + p0.z * v2.x + p0.w * v3.x;
            O[0][1] += p0.x * v0.y + p0.y * v1.y + p0.z * v2.y + p0.w * v3.y;
            O[1][0] += p1.x * v0.x + p1.y * v1.x + p1.z * v2.x + p1.w * v3.x;
            O[1][1] += p1.x * v0.y + p1.y * v1.y + p1.z * v2.y + p1.w * v3.y;
            O[2][0] += p2.x * v0.x + p2.y * v1.x + p2.z * v2.x + p2.w * v3.x;
            O[2][1] += p2.x * v0.y + p2.y * v1.y + p2.z * v2.y + p2.w * v3.y;
            O[3][0] += p3.x * v0.x + p3.y * v1.x + p3.z * v2.x + p3.w * v3.x;
            O[3][1] += p3.x * v0.y + p3.y * v1.y + p3.z * v2.y + p3.w * v3.y;
        }
        __syncwarp();
    }

#pragma unroll
    for (int i = 0; i < 4; i++) {
        float inv = 1.0f / l_r[i];
        float2 o2 = make_float2(O[i][0] * inv, O[i][1] * inv);
        *(float2*)&att[(size_t)(b * Mn + q0 + ty * 4 + i) * Dn + h * DKn + tx * 2] = o2;
    }
}

// ---------------- s head part 1: per (b,q,k) LN over H + projection ----------------
__global__ void spool_kernel(const float* __restrict__ scores, const float* __restrict__ snw,
                             const float* __restrict__ snb, const float* __restrict__ sfpw,
                             const float* __restrict__ sfpb, float* __restrict__ tmp) {
    size_t idx = (size_t)blockIdx.x * blockDim.x + threadIdx.x;
    if (idx >= (size_t)Bn * Mn * Mn) return;
    int k = idx % Mn;
    size_t r = idx / Mn;
    int qq = (int)(r % Mn);
    int b = (int)(r / Mn);
    float vals[8];
    float mu = 0.f;
#pragma unroll
    for (int h = 0; h < 8; h++) {
        vals[h] = scores[((size_t)(b * Hn + h) * Mn + qq) * Mn + k];
        mu += vals[h];
    }
    mu *= 0.125f;
    float var = 0.f;
#pragma unroll
    for (int h = 0; h < 8; h++) {
        float dd = vals[h] - mu;
        var += dd * dd;
    }
    var *= 0.125f;
    float rs = rsqrtf(var + 1e-5f);
    float o = sfpb[0];
#pragma unroll
    for (int h = 0; h < 8; h++) o += ((vals[h] - mu) * rs * snw[h] + snb[h]) * sfpw[h];
    tmp[idx] = o;
}

// ---------------- s head part 2: symmetrize ----------------
__global__ void ssym_kernel(const float* __restrict__ tmp, float* __restrict__ out) {
    size_t idx = (size_t)blockIdx.x * blockDim.x + threadIdx.x;
    if (idx >= (size_t)Bn * Mn * Mn) return;
    int k = idx % Mn;
    size_t r = idx / Mn;
    int qq = (int)(r % Mn);
    int b = (int)(r / Mn);
    out[idx] = 0.5f * (tmp[idx] + tmp[((size_t)b * Mn + k) * Mn + qq]);
}

// =====================================================================
extern "C" void kernel_launch(void* const* d_in, const int* in_sizes, int n_in,
                              void* d_out, int out_size) {
    const float* X   = (const float*)d_in[0];
    const int*   mask= (const int*)d_in[1];
    const float* fW  = (const float*)d_in[2];
    const float* fb  = (const float*)d_in[3];
    const float* cW  = (const float*)d_in[4];
    const float* cb  = (const float*)d_in[5];
    const float* Wq  = (const float*)d_in[6];
    const float* bq  = (const float*)d_in[7];
    const float* Wk  = (const float*)d_in[8];
    const float* bk  = (const float*)d_in[9];
    const float* Wv  = (const float*)d_in[10];
    const float* bv  = (const float*)d_in[11];
    const float* Wo  = (const float*)d_in[12];
    const float* bo  = (const float*)d_in[13];
    const float* ln1w= (const float*)d_in[14];
    const float* ln1b= (const float*)d_in[15];
    const float* ln2w= (const float*)d_in[16];
    const float* ln2b= (const float*)d_in[17];
    const float* lnfw= (const float*)d_in[18];
    const float* lnfb= (const float*)d_in[19];
    const float* uw  = (const float*)d_in[20];
    const float* ub  = (const float*)d_in[21];
    const float* dw  = (const float*)d_in[22];
    const float* db  = (const float*)d_in[23];
    const float* finw= (const float*)d_in[24];
    const float* finb= (const float*)d_in[25];
    const float* snw = (const float*)d_in[26];
    const float* snb = (const float*)d_in[27];
    const float* sfpw= (const float*)d_in[28];
    const float* sfpb= (const float*)d_in[29];

    float *x, *xn, *q, *k, *v, *att, *hid, *scores, *stmp;
    cudaGetSymbolAddress((void**)&x, g_x);
    cudaGetSymbolAddress((void**)&xn, g_xn);
    cudaGetSymbolAddress((void**)&q, g_q);
    cudaGetSymbolAddress((void**)&k, g_k);
    cudaGetSymbolAddress((void**)&v, g_v);
    cudaGetSymbolAddress((void**)&att, g_att);
    cudaGetSymbolAddress((void**)&hid, g_hid);
    cudaGetSymbolAddress((void**)&scores, g_scores);
    cudaGetSymbolAddress((void**)&stmp, g_stmp);

    const int BM = Bn * Mn;  // 4096 rows

    embed_kernel<<<BM, 256>>>(X, fW, fb, cW, cb);

    for (int i = 0; i < Ln; i++) {
        const float* Woi = Wo + (size_t)i * Dn * Dn;
        const float* uwi = uw + (size_t)i * Dn * DFFn;
        const float* dwi = dw + (size_t)i * DFFn * Dn;

        ln_kernel<<<BM, 256>>>(x, ln1w + i * Dn, ln1b + i * Dn, xn);

        dim3 gqkv(Dn / 128, BM / 128, 3);
        qkv_kernel<<<gqkv, 256>>>(xn,
                                  Wq + (size_t)i * Dn * Dn, bq + i * Dn,
                                  Wk + (size_t)i * Dn * Dn, bk + i * Dn,
                                  Wv + (size_t)i * Dn * Dn, bv + i * Dn,
                                  q, k, v);

        dim3 gfl(Mn / 64, Bn * Hn);
        if (i == Ln - 1)
            flash_kernel<true><<<gfl, 256>>>(q, k, v, mask, att, scores);
        else
            flash_kernel<false><<<gfl, 256>>>(q, k, v, mask, att, scores);

        dim3 go(Dn / 128, BM / 64);
        gemm_kernel<64, false, true><<<go, 256>>>(att, Woi, bo + i * Dn, x, x, Dn, Dn);

        ln_kernel<<<BM, 256>>>(x, ln2w + i * Dn, ln2b + i * Dn, xn);

        dim3 gu(DFFn / 128, BM / 128);
        gemm_kernel<128, true, false><<<gu, 256>>>(xn, uwi, ub + i * DFFn, nullptr, hid, DFFn, Dn);

        dim3 gd(Dn / 128, BM / 64);
        gemm_kernel<64, false, true><<<gd, 256>>>(hid, dwi, db + i * Dn, x, x, Dn, DFFn);
    }

    float* out_x = (float*)d_out;                    // (B, M, 64)
    float* out_s = out_x + (size_t)BM * 64;          // (B, M, M)

    ln_kernel<<<BM, 256>>>(x, lnfw, lnfb, xn);
    dim3 gf(1, BM / 64);
    gemm64n_kernel<<<gf, 256>>>(xn, finw, finb, out_x, 64, Dn);

    size_t npair = (size_t)Bn * Mn * Mn;
    int nb = (int)((npair + 255) / 256);
    spool_kernel<<<nb, 256>>>(scores, snw, snb, sfpw, sfpb, stmp);
    ssym_kernel<<<nb, 256>>>(stmp, out_s);
}

// round 4
// speedup vs baseline: 1.6490x; 1.0773x over previous
#include <cuda_runtime.h>
#include <math.h>
#include <stdint.h>

#define Bn 4
#define Mn 1024
#define Nn 70
#define Dn 256
#define Hn 8
#define Ln 4
#define DFFn 1024
#define DKn 32

// ---------------- scratch (no cudaMalloc allowed) ----------------
__device__ float g_x[Bn * Mn * Dn];
__device__ float g_xn[Bn * Mn * Dn];
__device__ float g_q[Bn * Mn * Dn];
__device__ float g_k[Bn * Mn * Dn];
__device__ float g_v[Bn * Mn * Dn];
__device__ float g_att[Bn * Mn * Dn];
__device__ float g_hid[Bn * Mn * DFFn];
__device__ float g_scores[(size_t)Bn * Hn * Mn * Mn];
__device__ float g_stmp[(size_t)Bn * Mn * Mn];

// ---------------- tf32 helpers ----------------
__device__ __forceinline__ uint32_t f2tf32(float x) {
    uint32_t u;
    asm("cvt.rna.tf32.f32 %0, %1;" : "=r"(u) : "f"(x));
    return u;
}

__device__ __forceinline__ void mma_tf32(float* acc, uint32_t a0, uint32_t a1,
                                         uint32_t a2, uint32_t a3,
                                         uint32_t b0, uint32_t b1) {
    asm("mma.sync.aligned.m16n8k8.row.col.f32.tf32.tf32.f32 "
        "{%0,%1,%2,%3}, {%4,%5,%6,%7}, {%8,%9}, {%0,%1,%2,%3};"
        : "+f"(acc[0]), "+f"(acc[1]), "+f"(acc[2]), "+f"(acc[3])
        : "r"(a0), "r"(a1), "r"(a2), "r"(a3), "r"(b0), "r"(b1));
}

// ---------------- embedding: fourier PE + char projection ----------------
__global__ void embed_kernel(const float* __restrict__ X,
                             const float* __restrict__ fW,
                             const float* __restrict__ fb,
                             const float* __restrict__ cW,
                             const float* __restrict__ cb) {
    int row = blockIdx.x;          // b*M + m
    int d = threadIdx.x;           // 0..255
    __shared__ float xr[Nn];
    if (d < Nn) xr[d] = X[(size_t)row * Nn + d];
    __syncthreads();

    int j = d & 127;
    float p = xr[0] * fW[j * 3 + 0] + xr[1] * fW[j * 3 + 1] + xr[2] * fW[j * 3 + 2] + fb[j];
    float pe = (d < 128 ? cosf(p) : sinf(p)) * 0.17677669529663687f;  // sqrt(2/64)

    float acc = cb[d] + pe;
#pragma unroll
    for (int c = 0; c < 64; c++) acc += xr[6 + c] * cW[c * Dn + d];
    g_x[(size_t)row * Dn + d] = acc;
}

// ---------------- layernorm over D=256, one block per row ----------------
__global__ void ln_kernel(const float* __restrict__ x,
                          const float* __restrict__ w,
                          const float* __restrict__ b,
                          float* __restrict__ out) {
    int row = blockIdx.x;
    int t = threadIdx.x;
    float v = x[(size_t)row * Dn + t];
    __shared__ float red[256];
    red[t] = v;
    __syncthreads();
    for (int s = 128; s > 0; s >>= 1) {
        if (t < s) red[t] += red[t + s];
        __syncthreads();
    }
    float mu = red[0] * (1.0f / Dn);
    __syncthreads();
    float dv = v - mu;
    red[t] = dv * dv;
    __syncthreads();
    for (int s = 128; s > 0; s >>= 1) {
        if (t < s) red[t] += red[t + s];
        __syncthreads();
    }
    float var = red[0] * (1.0f / Dn);
    float r = rsqrtf(var + 1e-5f);
    out[(size_t)row * Dn + t] = dv * r * w[t] + b[t];
}

// ---------------- tensor-core GEMM (tf32 hi/lo split, fp32-accurate) ----------------
// C[M x N] = A[M x K] @ B[K x N] + bias (+gelu) (+res)
// Block: 256 threads = 8 warps. BM in {64,128}, BN=128, BK=32.
template <int BM, int BN, bool GELU, bool RES>
__device__ __forceinline__ void tcgemm_dev(const float* __restrict__ A,
                                           const float* __restrict__ B,
                                           const float* __restrict__ bias,
                                           const float* __restrict__ res,
                                           float* __restrict__ C,
                                           int N, int K, int bm, int bn) {
    constexpr int WN = (BM == 128) ? 2 : 4;
    constexpr int WM = 8 / WN;
    constexpr int TM = BM / WM;   // 32
    constexpr int TN = BN / WN;   // 64 or 32
    constexpr int MT = TM / 16;   // 2
    constexpr int NT = TN / 8;    // 8 or 4

    __shared__ float As[32][BM + 4];   // [k][m]
    __shared__ float Bs[BN][36];       // [n][k], stride 36 -> conflict-free frag loads

    int tid = threadIdx.x;
    int lane = tid & 31, wid = tid >> 5;
    int wm = wid / WN, wn = wid % WN;
    int g = lane >> 2, t = lane & 3;

    float acc[MT][NT][4];
#pragma unroll
    for (int i = 0; i < MT; i++)
#pragma unroll
        for (int j = 0; j < NT; j++)
#pragma unroll
            for (int c = 0; c < 4; c++) acc[i][j][c] = 0.f;

    for (int k0 = 0; k0 < K; k0 += 32) {
        // load A tile (BM x 32) -> As[k][m]
#pragma unroll
        for (int p = 0; p < BM / 32; p++) {
            int idx = tid + p * 256;
            int m = idx >> 3, kq = (idx & 7) * 4;
            float4 a = *(const float4*)&A[(size_t)(bm + m) * K + k0 + kq];
            As[kq + 0][m] = a.x;
            As[kq + 1][m] = a.y;
            As[kq + 2][m] = a.z;
            As[kq + 3][m] = a.w;
        }
        // load B tile (32 x BN) -> Bs[n][k]
#pragma unroll
        for (int p = 0; p < BN / 32; p++) {
            int idx = tid + p * 256;
            int nq = (idx % (BN / 4)) * 4;
            int kk = idx / (BN / 4);
            float4 b4 = *(const float4*)&B[(size_t)(k0 + kk) * N + bn + nq];
            Bs[nq + 0][kk] = b4.x;
            Bs[nq + 1][kk] = b4.y;
            Bs[nq + 2][kk] = b4.z;
            Bs[nq + 3][kk] = b4.w;
        }
        __syncthreads();

#pragma unroll
        for (int ks = 0; ks < 4; ks++) {
            int c = ks * 8;
            uint32_t ahi[MT][4], alo[MT][4];
#pragma unroll
            for (int mt = 0; mt < MT; mt++) {
                int r = wm * TM + mt * 16 + g;
                float f0 = As[c + t][r];
                float f1 = As[c + t][r + 8];
                float f2 = As[c + t + 4][r];
                float f3 = As[c + t + 4][r + 8];
                ahi[mt][0] = f2tf32(f0);
                ahi[mt][1] = f2tf32(f1);
                ahi[mt][2] = f2tf32(f2);
                ahi[mt][3] = f2tf32(f3);
                alo[mt][0] = f2tf32(f0 - __uint_as_float(ahi[mt][0]));
                alo[mt][1] = f2tf32(f1 - __uint_as_float(ahi[mt][1]));
                alo[mt][2] = f2tf32(f2 - __uint_as_float(ahi[mt][2]));
                alo[mt][3] = f2tf32(f3 - __uint_as_float(ahi[mt][3]));
            }
#pragma unroll
            for (int nt = 0; nt < NT; nt++) {
                int n = wn * TN + nt * 8 + g;
                float fb0 = Bs[n][c + t];
                float fb1 = Bs[n][c + t + 4];
                uint32_t bh0 = f2tf32(fb0), bh1 = f2tf32(fb1);
                uint32_t bl0 = f2tf32(fb0 - __uint_as_float(bh0));
                uint32_t bl1 = f2tf32(fb1 - __uint_as_float(bh1));
#pragma unroll
                for (int mt = 0; mt < MT; mt++) {
                    mma_tf32(acc[mt][nt], ahi[mt][0], ahi[mt][1], ahi[mt][2], ahi[mt][3], bh0, bh1);
                    mma_tf32(acc[mt][nt], alo[mt][0], alo[mt][1], alo[mt][2], alo[mt][3], bh0, bh1);
                    mma_tf32(acc[mt][nt], ahi[mt][0], ahi[mt][1], ahi[mt][2], ahi[mt][3], bl0, bl1);
                }
            }
        }
        __syncthreads();
    }

    // epilogue
#pragma unroll
    for (int mt = 0; mt < MT; mt++) {
        int r0 = bm + wm * TM + mt * 16 + g;
#pragma unroll
        for (int nt = 0; nt < NT; nt++) {
            int col = bn + wn * TN + nt * 8 + t * 2;
            float b0 = bias[col], b1 = bias[col + 1];
#pragma unroll
            for (int half = 0; half < 2; half++) {
                int r = r0 + half * 8;
                float v0 = acc[mt][nt][half * 2 + 0] + b0;
                float v1 = acc[mt][nt][half * 2 + 1] + b1;
                if (GELU) {
                    v0 = 0.5f * v0 * (1.0f + erff(v0 * 0.70710678118654752f));
                    v1 = 0.5f * v1 * (1.0f + erff(v1 * 0.70710678118654752f));
                }
                if (RES) {
                    float2 rr = *(const float2*)&res[(size_t)r * N + col];
                    v0 += rr.x;
                    v1 += rr.y;
                }
                *(float2*)&C[(size_t)r * N + col] = make_float2(v0, v1);
            }
        }
    }
}

template <int BM, int BN, bool GELU, bool RES>
__global__ void tcgemm_kernel(const float* __restrict__ A, const float* __restrict__ B,
                              const float* __restrict__ bias, const float* __restrict__ res,
                              float* __restrict__ C, int N, int K) {
    tcgemm_dev<BM, BN, GELU, RES>(A, B, bias, res, C, N, K, blockIdx.y * BM, blockIdx.x * BN);
}

// QKV fused: blockIdx.z selects which of the three projections.
__global__ void qkv_kernel(const float* __restrict__ A,
                           const float* __restrict__ Wq, const float* __restrict__ bq,
                           const float* __restrict__ Wk, const float* __restrict__ bk,
                           const float* __restrict__ Wv, const float* __restrict__ bv,
                           float* __restrict__ q, float* __restrict__ k, float* __restrict__ v) {
    const float* B;
    const float* bias;
    float* C;
    if (blockIdx.z == 0) { B = Wq; bias = bq; C = q; }
    else if (blockIdx.z == 1) { B = Wk; bias = bk; C = k; }
    else { B = Wv; bias = bv; C = v; }
    tcgemm_dev<128, 128, false, false>(A, B, bias, nullptr, C, Dn, Dn,
                                       blockIdx.y * 128, blockIdx.x * 128);
}

// ---------------- small GEMM for final projection (N=64) ----------------
__global__ void gemm64n_kernel(const float* __restrict__ A, const float* __restrict__ B,
                               const float* __restrict__ bias, float* __restrict__ C,
                               int N, int K) {
    const int BM = 64, BN = 64, BK = 16;
    __shared__ float As[BM][BK + 1];
    __shared__ float Bs[BK][BN];
    int bm = blockIdx.y * BM, bn = blockIdx.x * BN;
    int tid = threadIdx.x;
    int ty = tid / 16, tx = tid % 16;
    float acc[4][4] = {};
    for (int k0 = 0; k0 < K; k0 += BK) {
#pragma unroll
        for (int i = 0; i < 4; i++) {
            int idx = tid + i * 256;
            int r = idx / BK, c = idx % BK;
            As[r][c] = A[(size_t)(bm + r) * K + k0 + c];
        }
#pragma unroll
        for (int i = 0; i < 4; i++) {
            int idx = tid + i * 256;
            int r = idx / BN, c = idx % BN;
            Bs[r][c] = B[(size_t)(k0 + r) * N + bn + c];
        }
        __syncthreads();
#pragma unroll
        for (int kk = 0; kk < BK; kk++) {
            float a[4], bb[4];
#pragma unroll
            for (int i = 0; i < 4; i++) a[i] = As[ty * 4 + i][kk];
#pragma unroll
            for (int j = 0; j < 4; j++) bb[j] = Bs[kk][tx * 4 + j];
#pragma unroll
            for (int i = 0; i < 4; i++)
#pragma unroll
                for (int j = 0; j < 4; j++) acc[i][j] += a[i] * bb[j];
        }
        __syncthreads();
    }
#pragma unroll
    for (int i = 0; i < 4; i++) {
        int r = bm + ty * 4 + i;
#pragma unroll
        for (int j = 0; j < 4; j++) {
            int cn = bn + tx * 4 + j;
            C[(size_t)r * N + cn] = acc[i][j] + bias[cn];
        }
    }
}

// ---------------- fused flash attention v2 (register-tiled) ----------------
template <bool SAVE>
__global__ void flash_kernel(const float* __restrict__ q, const float* __restrict__ k,
                             const float* __restrict__ v, const int* __restrict__ mask,
                             float* __restrict__ att, float* __restrict__ scores) {
    int bh = blockIdx.y;
    int b = bh / Hn, h = bh % Hn;
    int q0 = blockIdx.x * 64;
    __shared__ float Qs[64][33];
    __shared__ float Ks[64][33];
    __shared__ float Vs[64][34];
    __shared__ float Ps[64][68];
    int tid = threadIdx.x;
    int tx = tid & 15, ty = tid >> 4;

#pragma unroll
    for (int i = 0; i < 8; i++) {
        int idx = tid + i * 256;
        int r = idx >> 5, c = idx & 31;
        Qs[r][c] = q[(size_t)(b * Mn + q0 + r) * Dn + h * DKn + c];
    }

    float m_r[4], l_r[4];
    float O[4][2];
#pragma unroll
    for (int i = 0; i < 4; i++) {
        m_r[i] = -1e30f;
        l_r[i] = 0.f;
        O[i][0] = 0.f;
        O[i][1] = 0.f;
    }

    const float sc = 0.17677669529663687f;  // 1/sqrt(32)

    for (int kt = 0; kt < Mn; kt += 64) {
        __syncthreads();
#pragma unroll
        for (int i = 0; i < 8; i++) {
            int idx = tid + i * 256;
            int r = idx >> 5, c = idx & 31;
            size_t src = (size_t)(b * Mn + kt + r) * Dn + h * DKn + c;
            Ks[r][c] = k[src];
            Vs[r][c] = v[src];
        }
        __syncthreads();

        float S[4][4];
#pragma unroll
        for (int i = 0; i < 4; i++)
#pragma unroll
            for (int j = 0; j < 4; j++) S[i][j] = 0.f;
#pragma unroll
        for (int c = 0; c < 32; c++) {
            float a[4], bb[4];
#pragma unroll
            for (int i = 0; i < 4; i++) a[i] = Qs[ty * 4 + i][c];
#pragma unroll
            for (int j = 0; j < 4; j++) bb[j] = Ks[tx * 4 + j][c];
#pragma unroll
            for (int i = 0; i < 4; i++)
#pragma unroll
                for (int j = 0; j < 4; j++) S[i][j] += a[i] * bb[j];
        }
#pragma unroll
        for (int i = 0; i < 4; i++)
#pragma unroll
            for (int j = 0; j < 4; j++) S[i][j] *= sc;

        if (SAVE) {
#pragma unroll
            for (int i = 0; i < 4; i++) {
                size_t base = ((size_t)bh * Mn + q0 + ty * 4 + i) * Mn + kt + tx * 4;
                *(float4*)&scores[base] = make_float4(S[i][0], S[i][1], S[i][2], S[i][3]);
            }
        }

#pragma unroll
        for (int i = 0; i < 4; i++) {
            const int4 mr = *(const int4*)&mask[((size_t)(b * Mn + q0 + ty * 4 + i)) * Mn + kt + tx * 4];
            if (mr.x == 0) S[i][0] = -1e30f;
            if (mr.y == 0) S[i][1] = -1e30f;
            if (mr.z == 0) S[i][2] = -1e30f;
            if (mr.w == 0) S[i][3] = -1e30f;
        }

        float rs[4];
#pragma unroll
        for (int i = 0; i < 4; i++) {
            float mx = fmaxf(fmaxf(S[i][0], S[i][1]), fmaxf(S[i][2], S[i][3]));
#pragma unroll
            for (int off = 8; off > 0; off >>= 1)
                mx = fmaxf(mx, __shfl_xor_sync(0xFFFFFFFFu, mx, off));
            float newm = fmaxf(m_r[i], mx);
            float psum = 0.f;
#pragma unroll
            for (int j = 0; j < 4; j++) {
                S[i][j] = __expf(S[i][j] - newm);
                psum += S[i][j];
            }
#pragma unroll
            for (int off = 8; off > 0; off >>= 1)
                psum += __shfl_xor_sync(0xFFFFFFFFu, psum, off);
            rs[i] = __expf(m_r[i] - newm);
            l_r[i] = l_r[i] * rs[i] + psum;
            m_r[i] = newm;
            O[i][0] *= rs[i];
            O[i][1] *= rs[i];
        }

#pragma unroll
        for (int i = 0; i < 4; i++) {
            Ps[ty * 4 + i][tx * 4 + 0] = S[i][0];
            Ps[ty * 4 + i][tx * 4 + 1] = S[i][1];
            Ps[ty * 4 + i][tx * 4 + 2] = S[i][2];
            Ps[ty * 4 + i][tx * 4 + 3] = S[i][3];
        }
        __syncwarp();

#pragma unroll 4
        for (int kk = 0; kk < 64; kk += 4) {
            float4 p0 = *(const float4*)&Ps[ty * 4 + 0][kk];
            float4 p1 = *(const float4*)&Ps[ty * 4 + 1][kk];
            float4 p2 = *(const float4*)&Ps[ty * 4 + 2][kk];
            float4 p3 = *(const float4*)&Ps[ty * 4 + 3][kk];
            float2 v0 = *(const float2*)&Vs[kk + 0][tx * 2];
            float2 v1 = *(const float2*)&Vs[kk + 1][tx * 2];
            float2 v2 = *(const float2*)&Vs[kk + 2][tx * 2];
            float2 v3 = *(const float2*)&Vs[kk + 3][tx * 2];
            O[0][0] += p0.x * v0.x + p0.y * v1.x + p0.z * v2.x + p0.w * v3.x;
            O[0][1] += p0.x * v0.y + p0.y * v1.y + p0.z * v2.y + p0.w * v3.y;
            O[1][0] += p1.x * v0.x + p1.y * v1.x + p1.z * v2.x + p1.w * v3.x;
            O[1][1] += p1.x * v0.y + p1.y * v1.y + p1.z * v2.y + p1.w * v3.y;
            O[2][0] += p2.x * v0.x + p2.y * v1.x + p2.z * v2.x + p2.w * v3.x;
            O[2][1] += p2.x * v0.y + p2.y * v1.y + p2.z * v2.y + p2.w * v3.y;
            O[3][0] += p3.x * v0.x + p3.y * v1.x + p3.z * v2.x + p3.w * v3.x;
            O[3][1] += p3.x * v0.y + p3.y * v1.y + p3.z * v2.y + p3.w * v3.y;
        }
        __syncwarp();
    }

#pragma unroll
    for (int i = 0; i < 4; i++) {
        float inv = 1.0f / l_r[i];
        float2 o2 = make_float2(O[i][0] * inv, O[i][1] * inv);
        *(float2*)&att[(size_t)(b * Mn + q0 + ty * 4 + i) * Dn + h * DKn + tx * 2] = o2;
    }
}

// ---------------- s head part 1: per (b,q,k) LN over H + projection ----------------
__global__ void spool_kernel(const float* __restrict__ scores, const float* __restrict__ snw,
                             const float* __restrict__ snb, const float* __restrict__ sfpw,
                             const float* __restrict__ sfpb, float* __restrict__ tmp) {
    size_t idx = (size_t)blockIdx.x * blockDim.x + threadIdx.x;
    if (idx >= (size_t)Bn * Mn * Mn) return;
    int k = idx % Mn;
    size_t r = idx / Mn;
    int qq = (int)(r % Mn);
    int b = (int)(r / Mn);
    float vals[8];
    float mu = 0.f;
#pragma unroll
    for (int h = 0; h < 8; h++) {
        vals[h] = scores[((size_t)(b * Hn + h) * Mn + qq) * Mn + k];
        mu += vals[h];
    }
    mu *= 0.125f;
    float var = 0.f;
#pragma unroll
    for (int h = 0; h < 8; h++) {
        float dd = vals[h] - mu;
        var += dd * dd;
    }
    var *= 0.125f;
    float rs = rsqrtf(var + 1e-5f);
    float o = sfpb[0];
#pragma unroll
    for (int h = 0; h < 8; h++) o += ((vals[h] - mu) * rs * snw[h] + snb[h]) * sfpw[h];
    tmp[idx] = o;
}

// ---------------- s head part 2: symmetrize ----------------
__global__ void ssym_kernel(const float* __restrict__ tmp, float* __restrict__ out) {
    size_t idx = (size_t)blockIdx.x * blockDim.x + threadIdx.x;
    if (idx >= (size_t)Bn * Mn * Mn) return;
    int k = idx % Mn;
    size_t r = idx / Mn;
    int qq = (int)(r % Mn);
    int b = (int)(r / Mn);
    out[idx] = 0.5f * (tmp[idx] + tmp[((size_t)b * Mn + k) * Mn + qq]);
}

// =====================================================================
extern "C" void kernel_launch(void* const* d_in, const int* in_sizes, int n_in,
                              void* d_out, int out_size) {
    const float* X   = (const float*)d_in[0];
    const int*   mask= (const int*)d_in[1];
    const float* fW  = (const float*)d_in[2];
    const float* fb  = (const float*)d_in[3];
    const float* cW  = (const float*)d_in[4];
    const float* cb  = (const float*)d_in[5];
    const float* Wq  = (const float*)d_in[6];
    const float* bq  = (const float*)d_in[7];
    const float* Wk  = (const float*)d_in[8];
    const float* bk  = (const float*)d_in[9];
    const float* Wv  = (const float*)d_in[10];
    const float* bv  = (const float*)d_in[11];
    const float* Wo  = (const float*)d_in[12];
    const float* bo  = (const float*)d_in[13];
    const float* ln1w= (const float*)d_in[14];
    const float* ln1b= (const float*)d_in[15];
    const float* ln2w= (const float*)d_in[16];
    const float* ln2b= (const float*)d_in[17];
    const float* lnfw= (const float*)d_in[18];
    const float* lnfb= (const float*)d_in[19];
    const float* uw  = (const float*)d_in[20];
    const float* ub  = (const float*)d_in[21];
    const float* dw  = (const float*)d_in[22];
    const float* db  = (const float*)d_in[23];
    const float* finw= (const float*)d_in[24];
    const float* finb= (const float*)d_in[25];
    const float* snw = (const float*)d_in[26];
    const float* snb = (const float*)d_in[27];
    const float* sfpw= (const float*)d_in[28];
    const float* sfpb= (const float*)d_in[29];

    float *x, *xn, *q, *k, *v, *att, *hid, *scores, *stmp;
    cudaGetSymbolAddress((void**)&x, g_x);
    cudaGetSymbolAddress((void**)&xn, g_xn);
    cudaGetSymbolAddress((void**)&q, g_q);
    cudaGetSymbolAddress((void**)&k, g_k);
    cudaGetSymbolAddress((void**)&v, g_v);
    cudaGetSymbolAddress((void**)&att, g_att);
    cudaGetSymbolAddress((void**)&hid, g_hid);
    cudaGetSymbolAddress((void**)&scores, g_scores);
    cudaGetSymbolAddress((void**)&stmp, g_stmp);

    const int BM = Bn * Mn;  // 4096 rows

    embed_kernel<<<BM, 256>>>(X, fW, fb, cW, cb);

    for (int i = 0; i < Ln; i++) {
        const float* Woi = Wo + (size_t)i * Dn * Dn;
        const float* uwi = uw + (size_t)i * Dn * DFFn;
        const float* dwi = dw + (size_t)i * DFFn * Dn;

        ln_kernel<<<BM, 256>>>(x, ln1w + i * Dn, ln1b + i * Dn, xn);

        dim3 gqkv(Dn / 128, BM / 128, 3);
        qkv_kernel<<<gqkv, 256>>>(xn,
                                  Wq + (size_t)i * Dn * Dn, bq + i * Dn,
                                  Wk + (size_t)i * Dn * Dn, bk + i * Dn,
                                  Wv + (size_t)i * Dn * Dn, bv + i * Dn,
                                  q, k, v);

        dim3 gfl(Mn / 64, Bn * Hn);
        if (i == Ln - 1)
            flash_kernel<true><<<gfl, 256>>>(q, k, v, mask, att, scores);
        else
            flash_kernel<false><<<gfl, 256>>>(q, k, v, mask, att, scores);

        dim3 go(Dn / 128, BM / 64);
        tcgemm_kernel<64, 128, false, true><<<go, 256>>>(att, Woi, bo + i * Dn, x, x, Dn, Dn);

        ln_kernel<<<BM, 256>>>(x, ln2w + i * Dn, ln2b + i * Dn, xn);

        dim3 gu(DFFn / 128, BM / 128);
        tcgemm_kernel<128, 128, true, false><<<gu, 256>>>(xn, uwi, ub + i * DFFn, nullptr, hid, DFFn, Dn);

        dim3 gd(Dn / 128, BM / 64);
        tcgemm_kernel<64, 128, false, true><<<gd, 256>>>(hid, dwi, db + i * Dn, x, x, Dn, DFFn);
    }

    float* out_x = (float*)d_out;                    // (B, M, 64)
    float* out_s = out_x + (size_t)BM * 64;          // (B, M, M)

    ln_kernel<<<BM, 256>>>(x, lnfw, lnfb, xn);
    dim3 gf(1, BM / 64);
    gemm64n_kernel<<<gf, 256>>>(xn, finw, finb, out_x, 64, Dn);

    size_t npair = (size_t)Bn * Mn * Mn;
    int nb = (int)((npair + 255) / 256);
    spool_kernel<<<nb, 256>>>(scores, snw, snb, sfpw, sfpb, stmp);
    ssym_kernel<<<nb, 256>>>(stmp, out_s);
}